// round 12
// baseline (speedup 1.0000x reference)
#include <cuda_runtime.h>
#include <cstdint>
#include <mma.h>
#include <math.h>

using namespace nvcuda;

#define SB   128      // batch (graphs)
#define NN   512      // nodes per graph
#define PF   92       // node feature dim
#define K0   604      // PF + NN
#define DD   128      // hidden dim of GCN layers
#define HID  256
#define MAXD 96
#define ROWS (SB*NN)  // 65536

// ---------------- scratch (static device globals; no allocations) -----------
__device__ float g_dinv[ROWS];
__device__ int   g_cnt[ROWS];
__device__ int   g_nbr[(size_t)ROWS*MAXD];
__device__ float g_x[(size_t)ROWS*DD];   // post-aggregation activations
__device__ float g_y[(size_t)ROWS*DD];   // pre-aggregation (XW) results
__device__ __align__(16) float g_zero4[4];   // zero-filled quad for OOB cp.async

// ---------------- cp.async helpers ------------------------------------------
__device__ __forceinline__ void cp16(void* smem_dst, const void* gmem_src) {
    unsigned int s = (unsigned int)__cvta_generic_to_shared(smem_dst);
    asm volatile("cp.async.cg.shared.global [%0], [%1], 16;\n" :: "r"(s), "l"(gmem_src));
}
__device__ __forceinline__ void cp_commit() {
    asm volatile("cp.async.commit_group;\n" ::: "memory");
}
__device__ __forceinline__ void cp_wait1() {
    asm volatile("cp.async.wait_group 1;\n" ::: "memory");
}

// ---------------- 1) adjacency lists + deg^{-1/2} ---------------------------
// Ahat = (conn!=0) + I (diag may be 2 -> self index appears twice in list).
// int4 loads (LDG.128). List order is lane-major within each 128-col chunk —
// arbitrary order is fine, aggregation is a sum.
__global__ void build_adj(const int* __restrict__ conn) {
    int warp = (blockIdx.x * blockDim.x + threadIdx.x) >> 5;
    int lane = threadIdx.x & 31;
    if (warp >= ROWS) return;
    int i = warp & (NN - 1);
    const int4* row4 = (const int4*)(conn + (size_t)warp * NN);
    int cnt = 0;
    #pragma unroll
    for (int t = 0; t < 4; t++) {
        int4 v4 = row4[lane + t * 32];
        int vv[4] = {v4.x, v4.y, v4.z, v4.w};
        #pragma unroll
        for (int w = 0; w < 4; w++) {
            int v = (vv[w] != 0);
            unsigned m = __ballot_sync(0xffffffffu, v);
            if (v) {
                int pos = cnt + __popc(m & ((1u << lane) - 1u));
                if (pos < MAXD - 1)
                    g_nbr[(size_t)warp * MAXD + pos] = (lane + t * 32) * 4 + w;
            }
            cnt += __popc(m);
        }
    }
    if (lane == 0) {
        int c = cnt < (MAXD - 1) ? cnt : (MAXD - 1);
        g_nbr[(size_t)warp * MAXD + c] = i;   // self loop (the +I)
        g_cnt[warp] = c + 1;
        g_dinv[warp] = rsqrtf((float)(cnt + 1));
    }
}

// ---------------- 2) tf32 WMMA GEMM, cp.async 3-stage pipeline --------------
// g_y(65536 x 128) = A @ W.  Block: 256 thr, tile 128x128, warp 64x32, KT=32.
// fp32 staged raw via cp.async; RN tf32 rounding applied IN REGISTERS.
#define KT      32
#define A_LD    36
#define B_LD    132
#define A_STG   (128 * A_LD)       // floats per A stage
#define B_STG   (KT * B_LD)        // floats per B stage
#define GEMM_SMEM_BYTES ((3 * (A_STG + B_STG)) * 4)   // 105984

template<class Frag>
__device__ __forceinline__ void round_tf32(Frag& f) {
    #pragma unroll
    for (int i = 0; i < f.num_elements; i++)
        f.x[i] = wmma::__float_to_tf32(f.x[i]);
}

template<int KDIM, bool CONCAT>
__global__ void __launch_bounds__(256, 2)
gemm_wmma(const float* __restrict__ A0,   // node (CONCAT) / unused
          const float* __restrict__ A1,   // bond (CONCAT) / unused
          const float* __restrict__ W) {
    constexpr int NT = (KDIM + KT - 1) / KT;
    extern __shared__ float smem[];
    float* Abase = smem;                  // 3 stages of A
    float* Bbase = smem + 3 * A_STG;      // 3 stages of B

    int tid  = threadIdx.x;
    int warp = tid >> 5;
    int wm   = warp & 1;            // 2 warp rows of 64
    int wn   = warp >> 1;           // 4 warp cols of 32
    int rowbase = blockIdx.x * 128;

    wmma::fragment<wmma::accumulator, 16, 16, 8, float> acc[4][2];
    #pragma unroll
    for (int a = 0; a < 4; a++)
        #pragma unroll
        for (int b = 0; b < 2; b++)
            wmma::fill_fragment(acc[a][b], 0.0f);

    auto stage_load = [&](int kt, int st) {
        int kbase = kt * KT;
        float* As = Abase + st * A_STG;
        float* Bs = Bbase + st * B_STG;
        // A tile: 128 rows x 32 cols = 1024 16B chunks, 4 per thread
        #pragma unroll
        for (int q = 0; q < 4; q++) {
            int c  = q * 256 + tid;
            int m  = c >> 3;
            int k4 = (c & 7) << 2;
            int kg = kbase + k4;
            const float* src;
            if (CONCAT) {
                int r = rowbase + m;
                if (kg < PF)      src = A0 + (size_t)r * PF + kg;
                else if (kg < K0) src = A1 + (size_t)r * NN + (kg - PF);
                else              src = g_zero4;
            } else {
                src = g_x + (((size_t)(rowbase + m)) << 7) + kg;   // KDIM=128
            }
            cp16(&As[m * A_LD + k4], src);
        }
        // B tile: 32 rows x 128 cols = 1024 chunks, 4 per thread
        #pragma unroll
        for (int q = 0; q < 4; q++) {
            int c  = q * 256 + tid;
            int k  = c >> 5;
            int n4 = (c & 31) << 2;
            int kg = kbase + k;
            const float* src = (kg < KDIM) ? (W + (size_t)kg * DD + n4)
                                           : (const float*)g_zero4;
            cp16(&Bs[k * B_LD + n4], src);
        }
    };

    stage_load(0, 0); cp_commit();
    stage_load(1, 1); cp_commit();

    for (int kt = 0; kt < NT; kt++) {
        int buf = kt % 3;
        cp_wait1();            // tile kt resident (always-commit keeps count exact)
        __syncthreads();       // also guards buf (kt+2)%3 == (kt-1)%3 reuse below
        if (kt + 2 < NT) stage_load(kt + 2, (kt + 2) % 3);
        cp_commit();           // empty group in the tail keeps wait_group math valid
        const float* As = Abase + buf * A_STG;
        const float* Bs = Bbase + buf * B_STG;
        #pragma unroll
        for (int kf = 0; kf < 4; kf++) {
            wmma::fragment<wmma::matrix_a, 16, 16, 8, wmma::precision::tf32, wmma::row_major> af[4];
            wmma::fragment<wmma::matrix_b, 16, 16, 8, wmma::precision::tf32, wmma::row_major> bf[2];
            #pragma unroll
            for (int a = 0; a < 4; a++) {
                wmma::load_matrix_sync(af[a], As + (wm * 64 + a * 16) * A_LD + kf * 8, A_LD);
                round_tf32(af[a]);   // RN tf32 (cvt.rna) — kills truncation bias
            }
            #pragma unroll
            for (int b = 0; b < 2; b++) {
                wmma::load_matrix_sync(bf[b], Bs + (kf * 8) * B_LD + wn * 32 + b * 16, B_LD);
                round_tf32(bf[b]);
            }
            #pragma unroll
            for (int a = 0; a < 4; a++)
                #pragma unroll
                for (int b = 0; b < 2; b++)
                    wmma::mma_sync(acc[a][b], af[a], bf[b], acc[a][b]);
        }
    }

    #pragma unroll
    for (int a = 0; a < 4; a++)
        #pragma unroll
        for (int b = 0; b < 2; b++) {
            float* p = g_y + (size_t)(rowbase + wm * 64 + a * 16) * DD + wn * 32 + b * 16;
            wmma::store_matrix_sync(p, acc[a][b], DD, wmma::mem_row_major);
        }
}

// ---------------- 3) sparse normalized aggregation + bias -------------------
// Block = (graph s, 32-feature slab) -> 64KB smem, 2 blocks/SM so staging
// (DRAM) of one block overlaps gather (LDS) of the other.
// Stage ysh[j] = dinv[j]*y[j] (source scaling folded). Warp = row; lane = one
// feature (LDS.32, conflict-free).
#define FB 32
#define AGG_SMEM_BYTES (NN * FB * 4)   // 65536
__global__ void __launch_bounds__(512, 2)
aggregate(const float* __restrict__ bias) {
    extern __shared__ float ysh[];   // NN * 32 floats
    int s   = blockIdx.x;
    int f0  = blockIdx.y * FB;
    int tid = threadIdx.x;
    int lane = tid & 31, warp = tid >> 5;
    size_t sbase = (size_t)s * NN;

    // stage + pre-scale by source dinv (8 float4 per row, 512 rows)
    #pragma unroll
    for (int q = 0; q < 8; q++) {
        int e = q * 512 + tid;
        int r = e >> 3, c = (e & 7) << 2;
        float4 v = *(const float4*)&g_y[((sbase + r) << 7) + f0 + c];
        float d = g_dinv[sbase + r];
        v.x *= d; v.y *= d; v.z *= d; v.w *= d;
        *(float4*)&ysh[(r << 5) + c] = v;
    }
    __syncthreads();

    float bl = bias[f0 + lane];

    for (int r = warp; r < NN; r += 16) {
        int cnt = g_cnt[sbase + r];
        const int* nb = g_nbr + (size_t)(sbase + r) * MAXD;
        float acc = 0.0f;
        for (int base = 0; base < cnt; base += 32) {
            int my = base + lane;
            int idx = (my < cnt) ? nb[my] : 0;
            int lim = min(32, cnt - base);
            #pragma unroll 4
            for (int k = 0; k < lim; k++) {
                int j = __shfl_sync(0xffffffffu, idx, k);
                acc += ysh[(j << 5) + lane];
            }
        }
        float di = g_dinv[sbase + r];
        g_x[((sbase + r) << 7) + f0 + lane] = di * acc + bl;
    }
}

// ---------------- 4) pool + softplus + MLP head ------------------------------
__global__ void head_kernel(const float* __restrict__ Wh, const float* __restrict__ bh,
                            const float* __restrict__ Wi, const float* __restrict__ bi,
                            const float* __restrict__ We, const float* __restrict__ be,
                            const float* __restrict__ Wlb, const float* __restrict__ blb,
                            const float* __restrict__ Wub, const float* __restrict__ bub,
                            float* __restrict__ out) {
    __shared__ float part[256];
    __shared__ float sp[DD];
    __shared__ float hsh[HID];
    int s = blockIdx.x, tid = threadIdx.x;
    int f = tid & (DD - 1);
    int half = tid >> 7;
    size_t base = (size_t)s * NN * DD;
    float acc = 0.0f;
    for (int i = half * 256; i < half * 256 + 256; i++)
        acc += g_x[base + (size_t)i * DD + f];
    part[tid] = acc;
    __syncthreads();
    if (tid < DD) {
        float v = part[tid] + part[tid + 128];
        sp[tid] = (v > 20.0f) ? v : log1pf(expf(v));
    }
    __syncthreads();
    {
        float a = bh[tid];
        #pragma unroll 4
        for (int k = 0; k < DD; k++) a += sp[k] * Wh[k * HID + tid];
        hsh[tid] = a;
    }
    __syncthreads();
    if (tid < 100) {
        float a = bi[tid];
        #pragma unroll 4
        for (int k = 0; k < HID; k++) a += hsh[k] * Wi[k * 100 + tid];
        out[s * 100 + tid] = a;
    } else if (tid < 103) {
        const float* Wv = (tid == 100) ? We : (tid == 101) ? Wlb : Wub;
        float bv = (tid == 100) ? be[0] : (tid == 101) ? blb[0] : bub[0];
        float a = bv;
        for (int k = 0; k < HID; k++) a += hsh[k] * Wv[k];
        out[SB * 100 + (tid - 100) * SB + s] = a;
    }
}

// ---------------- launch -----------------------------------------------------
extern "C" void kernel_launch(void* const* d_in, const int* in_sizes, int n_in,
                              void* d_out, int out_size) {
    const float* node = (const float*)d_in[0];
    const float* bond = (const float*)d_in[1];
    const int*   conn = (const int*)d_in[2];
    // d_in[3] = batchAssign (implicit; unused)
    const float* W0 = (const float*)d_in[4];
    const float* b0 = (const float*)d_in[5];
    const float* W1 = (const float*)d_in[6];
    const float* b1 = (const float*)d_in[7];
    const float* W2 = (const float*)d_in[8];
    const float* b2 = (const float*)d_in[9];
    const float* Wh = (const float*)d_in[10];
    const float* bh = (const float*)d_in[11];
    const float* Wi = (const float*)d_in[12];
    const float* bi = (const float*)d_in[13];
    const float* We = (const float*)d_in[14];
    const float* be = (const float*)d_in[15];
    const float* Wlb = (const float*)d_in[16];
    const float* blb = (const float*)d_in[17];
    const float* Wub = (const float*)d_in[18];
    const float* bub = (const float*)d_in[19];
    float* out = (float*)d_out;

    // One-time idempotent configuration (host-side, not a stream op).
    static bool configured = false;
    if (!configured) {
        cudaFuncSetAttribute(aggregate, cudaFuncAttributeMaxDynamicSharedMemorySize, AGG_SMEM_BYTES);
        cudaFuncSetAttribute(gemm_wmma<K0, true>,
                             cudaFuncAttributeMaxDynamicSharedMemorySize, GEMM_SMEM_BYTES);
        cudaFuncSetAttribute(gemm_wmma<DD, false>,
                             cudaFuncAttributeMaxDynamicSharedMemorySize, GEMM_SMEM_BYTES);
        configured = true;
    }

    dim3 aggGrid(SB, DD / FB);   // (128, 4)

    build_adj<<<ROWS / 8, 256>>>(conn);

    gemm_wmma<K0, true><<<ROWS / 128, 256, GEMM_SMEM_BYTES>>>(node, bond, W0);
    aggregate<<<aggGrid, 512, AGG_SMEM_BYTES>>>(b0);

    gemm_wmma<DD, false><<<ROWS / 128, 256, GEMM_SMEM_BYTES>>>(nullptr, nullptr, W1);
    aggregate<<<aggGrid, 512, AGG_SMEM_BYTES>>>(b1);

    gemm_wmma<DD, false><<<ROWS / 128, 256, GEMM_SMEM_BYTES>>>(nullptr, nullptr, W2);
    aggregate<<<aggGrid, 512, AGG_SMEM_BYTES>>>(b2);

    head_kernel<<<SB, 256>>>(Wh, bh, Wi, bi, We, be, Wlb, blb, Wub, bub, out);
}

// round 13
// speedup vs baseline: 1.0344x; 1.0344x over previous
#include <cuda_runtime.h>
#include <cstdint>
#include <mma.h>
#include <math.h>

using namespace nvcuda;

#define SB   128      // batch (graphs)
#define NN   512      // nodes per graph
#define PF   92       // node feature dim
#define K0   604      // PF + NN
#define DD   128      // hidden dim of GCN layers
#define HID  256
#define MAXD 96
#define ROWS (SB*NN)  // 65536

// ---------------- scratch (static device globals; no allocations) -----------
__device__ float g_dinv[ROWS];
__device__ int   g_cnt[ROWS];
__device__ int   g_nbr[(size_t)ROWS*MAXD];
__device__ float g_x[(size_t)ROWS*DD];   // post-aggregation activations
__device__ float g_y[(size_t)ROWS*DD];   // pre-aggregation (XW) results
__device__ float g_w0r[K0*DD];           // tf32-pre-rounded weights
__device__ float g_w1r[DD*DD];
__device__ float g_w2r[DD*DD];
__device__ __align__(16) float g_zero4[4];   // zero-filled quad for OOB cp.async

// ---------------- cp.async helpers ------------------------------------------
__device__ __forceinline__ void cp16(void* smem_dst, const void* gmem_src) {
    unsigned int s = (unsigned int)__cvta_generic_to_shared(smem_dst);
    asm volatile("cp.async.cg.shared.global [%0], [%1], 16;\n" :: "r"(s), "l"(gmem_src));
}
__device__ __forceinline__ void cp_commit() {
    asm volatile("cp.async.commit_group;\n" ::: "memory");
}
__device__ __forceinline__ void cp_wait1() {
    asm volatile("cp.async.wait_group 1;\n" ::: "memory");
}

// ---------------- 0) pre-round weights to tf32 (RN) -------------------------
__global__ void round_weights(const float* __restrict__ W0,
                              const float* __restrict__ W1,
                              const float* __restrict__ W2) {
    int i = blockIdx.x * 256 + threadIdx.x;
    if (i < K0 * DD) g_w0r[i] = wmma::__float_to_tf32(W0[i]);
    if (i < DD * DD) {
        g_w1r[i] = wmma::__float_to_tf32(W1[i]);
        g_w2r[i] = wmma::__float_to_tf32(W2[i]);
    }
}

// ---------------- 1) adjacency lists + deg^{-1/2} ---------------------------
// Ahat = (conn!=0) + I (diag may be 2 -> self index appears twice in list).
// int4 loads (LDG.128); list order arbitrary (aggregation is a sum).
__global__ void build_adj(const int* __restrict__ conn) {
    int warp = (blockIdx.x * blockDim.x + threadIdx.x) >> 5;
    int lane = threadIdx.x & 31;
    if (warp >= ROWS) return;
    int i = warp & (NN - 1);
    const int4* row4 = (const int4*)(conn + (size_t)warp * NN);
    int cnt = 0;
    #pragma unroll
    for (int t = 0; t < 4; t++) {
        int4 v4 = row4[lane + t * 32];
        int vv[4] = {v4.x, v4.y, v4.z, v4.w};
        #pragma unroll
        for (int w = 0; w < 4; w++) {
            int v = (vv[w] != 0);
            unsigned m = __ballot_sync(0xffffffffu, v);
            if (v) {
                int pos = cnt + __popc(m & ((1u << lane) - 1u));
                if (pos < MAXD - 1)
                    g_nbr[(size_t)warp * MAXD + pos] = (lane + t * 32) * 4 + w;
            }
            cnt += __popc(m);
        }
    }
    if (lane == 0) {
        int c = cnt < (MAXD - 1) ? cnt : (MAXD - 1);
        g_nbr[(size_t)warp * MAXD + c] = i;   // self loop (the +I)
        g_cnt[warp] = c + 1;
        g_dinv[warp] = rsqrtf((float)(cnt + 1));
    }
}

// ---------------- 2) tf32 WMMA GEMM, cp.async 3-stage pipeline --------------
// g_y(65536 x 128) = A @ W.  Block: 256 thr, tile 128x128, warp 64x32, KT=32.
// B is pre-rounded tf32 (no cvt). A: CONCAT variant cvt's in registers;
// non-CONCAT reads g_x which aggregate already stored tf32-rounded (no cvt).
#define KT      32
#define A_LD    36
#define B_LD    132
#define A_STG   (128 * A_LD)       // floats per A stage
#define B_STG   (KT * B_LD)        // floats per B stage
#define GEMM_SMEM_BYTES ((3 * (A_STG + B_STG)) * 4)   // 105984

template<class Frag>
__device__ __forceinline__ void round_tf32(Frag& f) {
    #pragma unroll
    for (int i = 0; i < f.num_elements; i++)
        f.x[i] = wmma::__float_to_tf32(f.x[i]);
}

template<int KDIM, bool CONCAT>
__global__ void __launch_bounds__(256, 2)
gemm_wmma(const float* __restrict__ A0,   // node (CONCAT) / unused
          const float* __restrict__ A1,   // bond (CONCAT) / unused
          const float* __restrict__ W) {  // pre-rounded tf32 weights
    constexpr int NT = (KDIM + KT - 1) / KT;
    extern __shared__ float smem[];
    float* Abase = smem;                  // 3 stages of A
    float* Bbase = smem + 3 * A_STG;      // 3 stages of B

    int tid  = threadIdx.x;
    int warp = tid >> 5;
    int wm   = warp & 1;            // 2 warp rows of 64
    int wn   = warp >> 1;           // 4 warp cols of 32
    int rowbase = blockIdx.x * 128;

    wmma::fragment<wmma::accumulator, 16, 16, 8, float> acc[4][2];
    #pragma unroll
    for (int a = 0; a < 4; a++)
        #pragma unroll
        for (int b = 0; b < 2; b++)
            wmma::fill_fragment(acc[a][b], 0.0f);

    auto stage_load = [&](int kt, int st) {
        int kbase = kt * KT;
        float* As = Abase + st * A_STG;
        float* Bs = Bbase + st * B_STG;
        // A tile: 128 rows x 32 cols = 1024 16B chunks, 4 per thread
        #pragma unroll
        for (int q = 0; q < 4; q++) {
            int c  = q * 256 + tid;
            int m  = c >> 3;
            int k4 = (c & 7) << 2;
            int kg = kbase + k4;
            const float* src;
            if (CONCAT) {
                int r = rowbase + m;
                if (kg < PF)      src = A0 + (size_t)r * PF + kg;
                else if (kg < K0) src = A1 + (size_t)r * NN + (kg - PF);
                else              src = g_zero4;
            } else {
                src = g_x + (((size_t)(rowbase + m)) << 7) + kg;   // KDIM=128
            }
            cp16(&As[m * A_LD + k4], src);
        }
        // B tile: 32 rows x 128 cols = 1024 chunks, 4 per thread
        #pragma unroll
        for (int q = 0; q < 4; q++) {
            int c  = q * 256 + tid;
            int k  = c >> 5;
            int n4 = (c & 31) << 2;
            int kg = kbase + k;
            const float* src = (kg < KDIM) ? (W + (size_t)kg * DD + n4)
                                           : (const float*)g_zero4;
            cp16(&Bs[k * B_LD + n4], src);
        }
    };

    stage_load(0, 0); cp_commit();
    stage_load(1, 1); cp_commit();

    for (int kt = 0; kt < NT; kt++) {
        int buf = kt % 3;
        cp_wait1();            // tile kt resident (always-commit keeps count exact)
        __syncthreads();       // also guards buf (kt+2)%3 == (kt-1)%3 reuse below
        if (kt + 2 < NT) stage_load(kt + 2, (kt + 2) % 3);
        cp_commit();           // empty group in the tail keeps wait_group math valid
        const float* As = Abase + buf * A_STG;
        const float* Bs = Bbase + buf * B_STG;
        #pragma unroll
        for (int kf = 0; kf < 4; kf++) {
            wmma::fragment<wmma::matrix_a, 16, 16, 8, wmma::precision::tf32, wmma::row_major> af[4];
            wmma::fragment<wmma::matrix_b, 16, 16, 8, wmma::precision::tf32, wmma::row_major> bf[2];
            #pragma unroll
            for (int a = 0; a < 4; a++) {
                wmma::load_matrix_sync(af[a], As + (wm * 64 + a * 16) * A_LD + kf * 8, A_LD);
                if (CONCAT) round_tf32(af[a]);   // raw inputs need RN; g_x is pre-rounded
            }
            #pragma unroll
            for (int b = 0; b < 2; b++)
                wmma::load_matrix_sync(bf[b], Bs + (kf * 8) * B_LD + wn * 32 + b * 16, B_LD);
            #pragma unroll
            for (int a = 0; a < 4; a++)
                #pragma unroll
                for (int b = 0; b < 2; b++)
                    wmma::mma_sync(acc[a][b], af[a], bf[b], acc[a][b]);
        }
    }

    #pragma unroll
    for (int a = 0; a < 4; a++)
        #pragma unroll
        for (int b = 0; b < 2; b++) {
            float* p = g_y + (size_t)(rowbase + wm * 64 + a * 16) * DD + wn * 32 + b * 16;
            wmma::store_matrix_sync(p, acc[a][b], DD, wmma::mem_row_major);
        }
}

// ---------------- 3) sparse normalized aggregation + bias -------------------
// Round-11 layout: block = (graph, 64-feature half), 512 thr, 128KB smem.
// Stage ysh[j] = dinv[j]*y[j]; warp = row, lanes = features (LDS.64).
// do_round: RN-round output to tf32 when it feeds the next GEMM.
__global__ void __launch_bounds__(512, 1)
aggregate(const float* __restrict__ bias, int do_round) {
    extern __shared__ float ysh[];   // NN * 64 floats = 128KB
    int s   = blockIdx.x;
    int f0  = blockIdx.y * 64;
    int tid = threadIdx.x;
    int lane = tid & 31, warp = tid >> 5;
    size_t sbase = (size_t)s * NN;

    #pragma unroll
    for (int q = 0; q < 16; q++) {
        int e = q * 512 + tid;
        int r = e >> 4, c = e & 15;
        float4 v = *(const float4*)&g_y[((sbase + r) << 7) + f0 + (c << 2)];
        float d = g_dinv[sbase + r];
        v.x *= d; v.y *= d; v.z *= d; v.w *= d;
        *(float4*)&ysh[(r << 6) + (c << 2)] = v;
    }
    __syncthreads();

    float2 bl = *(const float2*)&bias[f0 + lane * 2];

    for (int r = warp; r < NN; r += 16) {
        int cnt = g_cnt[sbase + r];
        const int* nb = g_nbr + (size_t)(sbase + r) * MAXD;
        float accx = 0.0f, accy = 0.0f;
        for (int base = 0; base < cnt; base += 32) {
            int my = base + lane;
            int idx = (my < cnt) ? nb[my] : 0;
            int lim = min(32, cnt - base);
            #pragma unroll 4
            for (int k = 0; k < lim; k++) {
                int j = __shfl_sync(0xffffffffu, idx, k);
                float2 v = *(const float2*)&ysh[(j << 6) + lane * 2];
                accx += v.x; accy += v.y;
            }
        }
        float di = g_dinv[sbase + r];
        float2 o;
        o.x = di * accx + bl.x;
        o.y = di * accy + bl.y;
        if (do_round) {   // feeds a tf32 GEMM: pre-round (identical math, no gemm cvt)
            o.x = wmma::__float_to_tf32(o.x);
            o.y = wmma::__float_to_tf32(o.y);
        }
        *(float2*)&g_x[((sbase + r) << 7) + f0 + lane * 2] = o;
    }
}

// ---------------- 4) pool + softplus + MLP head ------------------------------
__global__ void head_kernel(const float* __restrict__ Wh, const float* __restrict__ bh,
                            const float* __restrict__ Wi, const float* __restrict__ bi,
                            const float* __restrict__ We, const float* __restrict__ be,
                            const float* __restrict__ Wlb, const float* __restrict__ blb,
                            const float* __restrict__ Wub, const float* __restrict__ bub,
                            float* __restrict__ out) {
    __shared__ float part[256];
    __shared__ float sp[DD];
    __shared__ float hsh[HID];
    int s = blockIdx.x, tid = threadIdx.x;
    int f = tid & (DD - 1);
    int half = tid >> 7;
    size_t base = (size_t)s * NN * DD;
    float acc = 0.0f;
    for (int i = half * 256; i < half * 256 + 256; i++)
        acc += g_x[base + (size_t)i * DD + f];
    part[tid] = acc;
    __syncthreads();
    if (tid < DD) {
        float v = part[tid] + part[tid + 128];
        sp[tid] = (v > 20.0f) ? v : log1pf(expf(v));
    }
    __syncthreads();
    {
        float a = bh[tid];
        #pragma unroll 4
        for (int k = 0; k < DD; k++) a += sp[k] * Wh[k * HID + tid];
        hsh[tid] = a;
    }
    __syncthreads();
    if (tid < 100) {
        float a = bi[tid];
        #pragma unroll 4
        for (int k = 0; k < HID; k++) a += hsh[k] * Wi[k * 100 + tid];
        out[s * 100 + tid] = a;
    } else if (tid < 103) {
        const float* Wv = (tid == 100) ? We : (tid == 101) ? Wlb : Wub;
        float bv = (tid == 100) ? be[0] : (tid == 101) ? blb[0] : bub[0];
        float a = bv;
        for (int k = 0; k < HID; k++) a += hsh[k] * Wv[k];
        out[SB * 100 + (tid - 100) * SB + s] = a;
    }
}

// ---------------- launch -----------------------------------------------------
extern "C" void kernel_launch(void* const* d_in, const int* in_sizes, int n_in,
                              void* d_out, int out_size) {
    const float* node = (const float*)d_in[0];
    const float* bond = (const float*)d_in[1];
    const int*   conn = (const int*)d_in[2];
    // d_in[3] = batchAssign (implicit; unused)
    const float* W0 = (const float*)d_in[4];
    const float* b0 = (const float*)d_in[5];
    const float* W1 = (const float*)d_in[6];
    const float* b1 = (const float*)d_in[7];
    const float* W2 = (const float*)d_in[8];
    const float* b2 = (const float*)d_in[9];
    const float* Wh = (const float*)d_in[10];
    const float* bh = (const float*)d_in[11];
    const float* Wi = (const float*)d_in[12];
    const float* bi = (const float*)d_in[13];
    const float* We = (const float*)d_in[14];
    const float* be = (const float*)d_in[15];
    const float* Wlb = (const float*)d_in[16];
    const float* blb = (const float*)d_in[17];
    const float* Wub = (const float*)d_in[18];
    const float* bub = (const float*)d_in[19];
    float* out = (float*)d_out;

    // One-time idempotent configuration (host-side, not stream ops).
    static bool configured = false;
    static float *w0r, *w1r, *w2r;
    if (!configured) {
        cudaFuncSetAttribute(aggregate, cudaFuncAttributeMaxDynamicSharedMemorySize, 131072);
        cudaFuncSetAttribute(gemm_wmma<K0, true>,
                             cudaFuncAttributeMaxDynamicSharedMemorySize, GEMM_SMEM_BYTES);
        cudaFuncSetAttribute(gemm_wmma<DD, false>,
                             cudaFuncAttributeMaxDynamicSharedMemorySize, GEMM_SMEM_BYTES);
        cudaGetSymbolAddress((void**)&w0r, g_w0r);
        cudaGetSymbolAddress((void**)&w1r, g_w1r);
        cudaGetSymbolAddress((void**)&w2r, g_w2r);
        configured = true;
    }

    dim3 aggGrid(SB, 2);

    round_weights<<<(K0 * DD + 255) / 256, 256>>>(W0, W1, W2);
    build_adj<<<ROWS / 8, 256>>>(conn);

    gemm_wmma<K0, true><<<ROWS / 128, 256, GEMM_SMEM_BYTES>>>(node, bond, w0r);
    aggregate<<<aggGrid, 512, 131072>>>(b0, 1);

    gemm_wmma<DD, false><<<ROWS / 128, 256, GEMM_SMEM_BYTES>>>(nullptr, nullptr, w1r);
    aggregate<<<aggGrid, 512, 131072>>>(b1, 1);

    gemm_wmma<DD, false><<<ROWS / 128, 256, GEMM_SMEM_BYTES>>>(nullptr, nullptr, w2r);
    aggregate<<<aggGrid, 512, 131072>>>(b2, 0);

    head_kernel<<<SB, 256>>>(Wh, bh, Wi, bi, We, be, Wlb, blb, Wub, bub, out);
}

// round 15
// speedup vs baseline: 1.0601x; 1.0248x over previous
#include <cuda_runtime.h>
#include <cstdint>
#include <mma.h>
#include <math.h>

using namespace nvcuda;

#define SB   128      // batch (graphs)
#define NN   512      // nodes per graph
#define PF   92       // node feature dim
#define K0   604      // PF + NN
#define DD   128      // hidden dim of GCN layers
#define HID  256
#define MAXD 96
#define ROWS (SB*NN)  // 65536

// ---------------- scratch (static device globals; no allocations) -----------
__device__ float g_dinv[ROWS];
__device__ int   g_cnt[ROWS];            // PADDED count (multiple of 8)
__device__ int   g_nbr[(size_t)ROWS*MAXD];
__device__ float g_x[(size_t)ROWS*DD];   // post-aggregation activations
__device__ float g_y[(size_t)ROWS*DD];   // pre-aggregation (XW) results
__device__ float g_w0r[K0*DD];           // tf32-pre-rounded weights
__device__ float g_w1r[DD*DD];
__device__ float g_w2r[DD*DD];
__device__ __align__(16) float g_zero4[4];   // zero-filled quad for OOB cp.async

// ---------------- helpers ----------------------------------------------------
__device__ __forceinline__ void cp16(void* smem_dst, const void* gmem_src) {
    unsigned int s = (unsigned int)__cvta_generic_to_shared(smem_dst);
    asm volatile("cp.async.cg.shared.global [%0], [%1], 16;\n" :: "r"(s), "l"(gmem_src));
}
__device__ __forceinline__ void cp_commit() {
    asm volatile("cp.async.commit_group;\n" ::: "memory");
}
__device__ __forceinline__ void cp_wait1() {
    asm volatile("cp.async.wait_group 1;\n" ::: "memory");
}
__device__ __forceinline__ void addf32x2(unsigned long long& acc, unsigned long long v) {
    asm("add.rn.f32x2 %0, %1, %2;" : "=l"(acc) : "l"(acc), "l"(v));
}

// ---------------- 0) pre-round weights to tf32 (RN) -------------------------
__global__ void round_weights(const float* __restrict__ W0,
                              const float* __restrict__ W1,
                              const float* __restrict__ W2) {
    int i = blockIdx.x * 256 + threadIdx.x;
    if (i < K0 * DD) g_w0r[i] = wmma::__float_to_tf32(W0[i]);
    if (i < DD * DD) {
        g_w1r[i] = wmma::__float_to_tf32(W1[i]);
        g_w2r[i] = wmma::__float_to_tf32(W2[i]);
    }
}

// ---------------- 1) adjacency lists + deg^{-1/2} ---------------------------
// Ahat = (conn!=0) + I (diag may be 2 -> self appears twice).
// List = real neighbors (capped 87) + self + sentinel NN pads to multiple of 8.
// g_cnt = padded count; dinv uses real degree.
__global__ void build_adj(const int* __restrict__ conn) {
    int warp = (blockIdx.x * blockDim.x + threadIdx.x) >> 5;
    int lane = threadIdx.x & 31;
    if (warp >= ROWS) return;
    int i = warp & (NN - 1);
    const int4* row4 = (const int4*)(conn + (size_t)warp * NN);
    int cnt = 0;
    #pragma unroll
    for (int t = 0; t < 4; t++) {
        int4 v4 = row4[lane + t * 32];
        int vv[4] = {v4.x, v4.y, v4.z, v4.w};
        #pragma unroll
        for (int w = 0; w < 4; w++) {
            int v = (vv[w] != 0);
            unsigned m = __ballot_sync(0xffffffffu, v);
            if (v) {
                int pos = cnt + __popc(m & ((1u << lane) - 1u));
                if (pos < MAXD - 9)
                    g_nbr[(size_t)warp * MAXD + pos] = (lane + t * 32) * 4 + w;
            }
            cnt += __popc(m);
        }
    }
    if (lane == 0) {
        int c = cnt < (MAXD - 9) ? cnt : (MAXD - 9);   // cap 87
        size_t b = (size_t)warp * MAXD;
        g_nbr[b + c] = i;   // self loop (the +I)
        c++;
        while (c & 7) g_nbr[b + c++] = NN;   // sentinel -> zero row
        g_cnt[warp] = c;
        g_dinv[warp] = rsqrtf((float)(cnt + 1));
    }
}

// ---------------- 2) tf32 WMMA GEMM, cp.async 3-stage pipeline --------------
#define KT      32
#define A_LD    36
#define B_LD    132
#define A_STG   (128 * A_LD)
#define B_STG   (KT * B_LD)
#define GEMM_SMEM_BYTES ((3 * (A_STG + B_STG)) * 4)   // 105984

template<class Frag>
__device__ __forceinline__ void round_tf32(Frag& f) {
    #pragma unroll
    for (int i = 0; i < f.num_elements; i++)
        f.x[i] = wmma::__float_to_tf32(f.x[i]);
}

template<int KDIM, bool CONCAT>
__global__ void __launch_bounds__(256, 2)
gemm_wmma(const float* __restrict__ A0,
          const float* __restrict__ A1,
          const float* __restrict__ W) {
    constexpr int NT = (KDIM + KT - 1) / KT;
    extern __shared__ float smem[];
    float* Abase = smem;
    float* Bbase = smem + 3 * A_STG;

    int tid  = threadIdx.x;
    int warp = tid >> 5;
    int wm   = warp & 1;
    int wn   = warp >> 1;
    int rowbase = blockIdx.x * 128;

    wmma::fragment<wmma::accumulator, 16, 16, 8, float> acc[4][2];
    #pragma unroll
    for (int a = 0; a < 4; a++)
        #pragma unroll
        for (int b = 0; b < 2; b++)
            wmma::fill_fragment(acc[a][b], 0.0f);

    auto stage_load = [&](int kt, int st) {
        int kbase = kt * KT;
        float* As = Abase + st * A_STG;
        float* Bs = Bbase + st * B_STG;
        #pragma unroll
        for (int q = 0; q < 4; q++) {
            int c  = q * 256 + tid;
            int m  = c >> 3;
            int k4 = (c & 7) << 2;
            int kg = kbase + k4;
            const float* src;
            if (CONCAT) {
                int r = rowbase + m;
                if (kg < PF)      src = A0 + (size_t)r * PF + kg;
                else if (kg < K0) src = A1 + (size_t)r * NN + (kg - PF);
                else              src = g_zero4;
            } else {
                src = g_x + (((size_t)(rowbase + m)) << 7) + kg;
            }
            cp16(&As[m * A_LD + k4], src);
        }
        #pragma unroll
        for (int q = 0; q < 4; q++) {
            int c  = q * 256 + tid;
            int k  = c >> 5;
            int n4 = (c & 31) << 2;
            int kg = kbase + k;
            const float* src = (kg < KDIM) ? (W + (size_t)kg * DD + n4)
                                           : (const float*)g_zero4;
            cp16(&Bs[k * B_LD + n4], src);
        }
    };

    stage_load(0, 0); cp_commit();
    stage_load(1, 1); cp_commit();

    for (int kt = 0; kt < NT; kt++) {
        int buf = kt % 3;
        cp_wait1();
        __syncthreads();
        if (kt + 2 < NT) stage_load(kt + 2, (kt + 2) % 3);
        cp_commit();
        const float* As = Abase + buf * A_STG;
        const float* Bs = Bbase + buf * B_STG;
        #pragma unroll
        for (int kf = 0; kf < 4; kf++) {
            wmma::fragment<wmma::matrix_a, 16, 16, 8, wmma::precision::tf32, wmma::row_major> af[4];
            wmma::fragment<wmma::matrix_b, 16, 16, 8, wmma::precision::tf32, wmma::row_major> bf[2];
            #pragma unroll
            for (int a = 0; a < 4; a++) {
                wmma::load_matrix_sync(af[a], As + (wm * 64 + a * 16) * A_LD + kf * 8, A_LD);
                if (CONCAT) round_tf32(af[a]);   // raw inputs need RN; g_x pre-rounded
            }
            #pragma unroll
            for (int b = 0; b < 2; b++)
                wmma::load_matrix_sync(bf[b], Bs + (kf * 8) * B_LD + wn * 32 + b * 16, B_LD);
            #pragma unroll
            for (int a = 0; a < 4; a++)
                #pragma unroll
                for (int b = 0; b < 2; b++)
                    wmma::mma_sync(acc[a][b], af[a], bf[b], acc[a][b]);
        }
    }

    #pragma unroll
    for (int a = 0; a < 4; a++)
        #pragma unroll
        for (int b = 0; b < 2; b++) {
            float* p = g_y + (size_t)(rowbase + wm * 64 + a * 16) * DD + wn * 32 + b * 16;
            wmma::store_matrix_sync(p, acc[a][b], DD, wmma::mem_row_major);
        }
}

// ---------------- 3) sparse normalized aggregation + bias -------------------
// Block = (graph, 64-feature half). ysh = 513 rows (row 512 = zeros, sentinel
// target). Padded lists -> branch-free unroll-8 inner loop with packed
// add.rn.f32x2 (1 instr / 2 features), 2 accumulators to break dep chain.
#define AGG_SMEM_BYTES ((NN + 1) * 64 * 4)   // 131328
__global__ void __launch_bounds__(512, 1)
aggregate(const float* __restrict__ bias, int do_round) {
    extern __shared__ float ysh[];   // (NN+1) x 64
    int s   = blockIdx.x;
    int f0  = blockIdx.y * 64;
    int tid = threadIdx.x;
    int lane = tid & 31, warp = tid >> 5;
    size_t sbase = (size_t)s * NN;

    #pragma unroll
    for (int q = 0; q < 16; q++) {
        int e = q * 512 + tid;
        int r = e >> 4, c = e & 15;
        float4 v = *(const float4*)&g_y[((sbase + r) << 7) + f0 + (c << 2)];
        float d = g_dinv[sbase + r];
        v.x *= d; v.y *= d; v.z *= d; v.w *= d;
        *(float4*)&ysh[(r << 6) + (c << 2)] = v;
    }
    if (tid < 64) ysh[(NN << 6) + tid] = 0.0f;   // sentinel zero row
    __syncthreads();

    const unsigned long long* ysh64 = (const unsigned long long*)ysh;
    float2 bl = *(const float2*)&bias[f0 + lane * 2];

    for (int r = warp; r < NN; r += 16) {
        int cnt = g_cnt[sbase + r];          // padded, multiple of 8
        const int* nb = g_nbr + (size_t)(sbase + r) * MAXD;
        unsigned long long a0 = 0ull, a1 = 0ull;
        for (int base = 0; base < cnt; base += 32) {
            int idx = nb[base + lane];       // list region always readable
            int n8 = min(32, cnt - base) >> 3;
            for (int c8 = 0; c8 < n8; c8++) {
                #pragma unroll
                for (int k = 0; k < 8; k++) {
                    int j = __shfl_sync(0xffffffffu, idx, c8 * 8 + k);
                    unsigned long long v = ysh64[((unsigned)j << 5) + lane];
                    if (k & 1) addf32x2(a1, v); else addf32x2(a0, v);
                }
            }
        }
        float2 f0v = *(float2*)&a0;
        float2 f1v = *(float2*)&a1;
        float di = g_dinv[sbase + r];
        float2 o;
        o.x = di * (f0v.x + f1v.x) + bl.x;
        o.y = di * (f0v.y + f1v.y) + bl.y;
        if (do_round) {
            o.x = wmma::__float_to_tf32(o.x);
            o.y = wmma::__float_to_tf32(o.y);
        }
        *(float2*)&g_x[((sbase + r) << 7) + f0 + lane * 2] = o;
    }
}

// ---------------- 4) pool + softplus + MLP head ------------------------------
__global__ void head_kernel(const float* __restrict__ Wh, const float* __restrict__ bh,
                            const float* __restrict__ Wi, const float* __restrict__ bi,
                            const float* __restrict__ We, const float* __restrict__ be,
                            const float* __restrict__ Wlb, const float* __restrict__ blb,
                            const float* __restrict__ Wub, const float* __restrict__ bub,
                            float* __restrict__ out) {
    __shared__ float part[256];
    __shared__ float sp[DD];
    __shared__ float hsh[HID];
    int s = blockIdx.x, tid = threadIdx.x;
    int f = tid & (DD - 1);
    int half = tid >> 7;
    size_t base = (size_t)s * NN * DD;
    float acc = 0.0f;
    for (int i = half * 256; i < half * 256 + 256; i++)
        acc += g_x[base + (size_t)i * DD + f];
    part[tid] = acc;
    __syncthreads();
    if (tid < DD) {
        float v = part[tid] + part[tid + 128];
        sp[tid] = (v > 20.0f) ? v : log1pf(expf(v));
    }
    __syncthreads();
    {
        float a = bh[tid];
        #pragma unroll 4
        for (int k = 0; k < DD; k++) a += sp[k] * Wh[k * HID + tid];
        hsh[tid] = a;
    }
    __syncthreads();
    if (tid < 100) {
        float a = bi[tid];
        #pragma unroll 4
        for (int k = 0; k < HID; k++) a += hsh[k] * Wi[k * 100 + tid];
        out[s * 100 + tid] = a;
    } else if (tid < 103) {
        const float* Wv = (tid == 100) ? We : (tid == 101) ? Wlb : Wub;
        float bv = (tid == 100) ? be[0] : (tid == 101) ? blb[0] : bub[0];
        float a = bv;
        for (int k = 0; k < HID; k++) a += hsh[k] * Wv[k];
        out[SB * 100 + (tid - 100) * SB + s] = a;
    }
}

// ---------------- launch -----------------------------------------------------
extern "C" void kernel_launch(void* const* d_in, const int* in_sizes, int n_in,
                              void* d_out, int out_size) {
    const float* node = (const float*)d_in[0];
    const float* bond = (const float*)d_in[1];
    const int*   conn = (const int*)d_in[2];
    const float* W0 = (const float*)d_in[4];
    const float* b0 = (const float*)d_in[5];
    const float* W1 = (const float*)d_in[6];
    const float* b1 = (const float*)d_in[7];
    const float* W2 = (const float*)d_in[8];
    const float* b2 = (const float*)d_in[9];
    const float* Wh = (const float*)d_in[10];
    const float* bh = (const float*)d_in[11];
    const float* Wi = (const float*)d_in[12];
    const float* bi = (const float*)d_in[13];
    const float* We = (const float*)d_in[14];
    const float* be = (const float*)d_in[15];
    const float* Wlb = (const float*)d_in[16];
    const float* blb = (const float*)d_in[17];
    const float* Wub = (const float*)d_in[18];
    const float* bub = (const float*)d_in[19];
    float* out = (float*)d_out;

    static bool configured = false;
    static float *w0r, *w1r, *w2r;
    if (!configured) {
        cudaFuncSetAttribute(aggregate, cudaFuncAttributeMaxDynamicSharedMemorySize, AGG_SMEM_BYTES);
        cudaFuncSetAttribute(gemm_wmma<K0, true>,
                             cudaFuncAttributeMaxDynamicSharedMemorySize, GEMM_SMEM_BYTES);
        cudaFuncSetAttribute(gemm_wmma<DD, false>,
                             cudaFuncAttributeMaxDynamicSharedMemorySize, GEMM_SMEM_BYTES);
        cudaGetSymbolAddress((void**)&w0r, g_w0r);
        cudaGetSymbolAddress((void**)&w1r, g_w1r);
        cudaGetSymbolAddress((void**)&w2r, g_w2r);
        configured = true;
    }

    dim3 aggGrid(SB, 2);

    round_weights<<<(K0 * DD + 255) / 256, 256>>>(W0, W1, W2);
    build_adj<<<ROWS / 8, 256>>>(conn);

    gemm_wmma<K0, true><<<ROWS / 128, 256, GEMM_SMEM_BYTES>>>(node, bond, w0r);
    aggregate<<<aggGrid, 512, AGG_SMEM_BYTES>>>(b0, 1);

    gemm_wmma<DD, false><<<ROWS / 128, 256, GEMM_SMEM_BYTES>>>(nullptr, nullptr, w1r);
    aggregate<<<aggGrid, 512, AGG_SMEM_BYTES>>>(b1, 1);

    gemm_wmma<DD, false><<<ROWS / 128, 256, GEMM_SMEM_BYTES>>>(nullptr, nullptr, w2r);
    aggregate<<<aggGrid, 512, AGG_SMEM_BYTES>>>(b2, 0);

    head_kernel<<<SB, 256>>>(Wh, bh, Wi, bi, We, be, Wlb, blb, Wub, bub, out);
}

// round 16
// speedup vs baseline: 1.1720x; 1.1056x over previous
#include <cuda_runtime.h>
#include <cstdint>
#include <mma.h>
#include <math.h>

using namespace nvcuda;

#define SB   128      // batch (graphs)
#define NN   512      // nodes per graph
#define PF   92       // node feature dim
#define K0   604      // PF + NN
#define DD   128      // hidden dim of GCN layers
#define HID  256
#define MAXD 96
#define ROWS (SB*NN)  // 65536

// ---------------- scratch (static device globals; no allocations) -----------
__device__ float g_dinv[ROWS];
__device__ int   g_cnt[ROWS];            // PADDED count (multiple of 8)
__device__ int   g_nbr[(size_t)ROWS*MAXD];
__device__ float g_x[(size_t)ROWS*DD];   // post-aggregation activations
__device__ float g_y[(size_t)ROWS*DD];   // pre-aggregation (XW) results
__device__ float g_w0r[K0*DD];           // tf32-pre-rounded weights
__device__ float g_w1r[DD*DD];
__device__ float g_w2r[DD*DD];
__device__ __align__(16) float g_zero4[4];   // zero-filled quad for OOB cp.async

// ---------------- helpers ----------------------------------------------------
__device__ __forceinline__ void cp16(void* smem_dst, const void* gmem_src) {
    unsigned int s = (unsigned int)__cvta_generic_to_shared(smem_dst);
    asm volatile("cp.async.cg.shared.global [%0], [%1], 16;\n" :: "r"(s), "l"(gmem_src));
}
__device__ __forceinline__ void cp_commit() {
    asm volatile("cp.async.commit_group;\n" ::: "memory");
}
__device__ __forceinline__ void cp_wait1() {
    asm volatile("cp.async.wait_group 1;\n" ::: "memory");
}
__device__ __forceinline__ void addf32x2(unsigned long long& acc, unsigned long long v) {
    asm("add.rn.f32x2 %0, %1, %2;" : "=l"(acc) : "l"(acc), "l"(v));
}

// ---------------- 0) pre-round weights to tf32 (RN) -------------------------
__global__ void round_weights(const float* __restrict__ W0,
                              const float* __restrict__ W1,
                              const float* __restrict__ W2) {
    int i = blockIdx.x * 256 + threadIdx.x;
    if (i < K0 * DD) g_w0r[i] = wmma::__float_to_tf32(W0[i]);
    if (i < DD * DD) {
        g_w1r[i] = wmma::__float_to_tf32(W1[i]);
        g_w2r[i] = wmma::__float_to_tf32(W2[i]);
    }
}

// ---------------- 1) adjacency lists + deg^{-1/2} ---------------------------
// Ahat = (conn!=0) + I (diag may be 2 -> self appears twice).
// List = real neighbors (capped 87) + self + sentinel NN pads to multiple of 8.
__global__ void build_adj(const int* __restrict__ conn) {
    int warp = (blockIdx.x * blockDim.x + threadIdx.x) >> 5;
    int lane = threadIdx.x & 31;
    if (warp >= ROWS) return;
    int i = warp & (NN - 1);
    const int4* row4 = (const int4*)(conn + (size_t)warp * NN);
    int cnt = 0;
    #pragma unroll
    for (int t = 0; t < 4; t++) {
        int4 v4 = row4[lane + t * 32];
        int vv[4] = {v4.x, v4.y, v4.z, v4.w};
        #pragma unroll
        for (int w = 0; w < 4; w++) {
            int v = (vv[w] != 0);
            unsigned m = __ballot_sync(0xffffffffu, v);
            if (v) {
                int pos = cnt + __popc(m & ((1u << lane) - 1u));
                if (pos < MAXD - 9)
                    g_nbr[(size_t)warp * MAXD + pos] = (lane + t * 32) * 4 + w;
            }
            cnt += __popc(m);
        }
    }
    if (lane == 0) {
        int c = cnt < (MAXD - 9) ? cnt : (MAXD - 9);   // cap 87
        size_t b = (size_t)warp * MAXD;
        g_nbr[b + c] = i;   // self loop (the +I)
        c++;
        while (c & 7) g_nbr[b + c++] = NN;   // sentinel -> zero row
        g_cnt[warp] = c;
        g_dinv[warp] = rsqrtf((float)(cnt + 1));
    }
}

// ---------------- 2) tf32 WMMA GEMM, cp.async 3-stage pipeline --------------
#define KT      32
#define A_LD    36
#define B_LD    132
#define A_STG   (128 * A_LD)
#define B_STG   (KT * B_LD)
#define GEMM_SMEM_BYTES ((3 * (A_STG + B_STG)) * 4)   // 105984

template<class Frag>
__device__ __forceinline__ void round_tf32(Frag& f) {
    #pragma unroll
    for (int i = 0; i < f.num_elements; i++)
        f.x[i] = wmma::__float_to_tf32(f.x[i]);
}

template<int KDIM, bool CONCAT>
__global__ void __launch_bounds__(256, 2)
gemm_wmma(const float* __restrict__ A0,
          const float* __restrict__ A1,
          const float* __restrict__ W) {
    constexpr int NT = (KDIM + KT - 1) / KT;
    extern __shared__ float smem[];
    float* Abase = smem;
    float* Bbase = smem + 3 * A_STG;

    int tid  = threadIdx.x;
    int warp = tid >> 5;
    int wm   = warp & 1;
    int wn   = warp >> 1;
    int rowbase = blockIdx.x * 128;

    wmma::fragment<wmma::accumulator, 16, 16, 8, float> acc[4][2];
    #pragma unroll
    for (int a = 0; a < 4; a++)
        #pragma unroll
        for (int b = 0; b < 2; b++)
            wmma::fill_fragment(acc[a][b], 0.0f);

    auto stage_load = [&](int kt, int st) {
        int kbase = kt * KT;
        float* As = Abase + st * A_STG;
        float* Bs = Bbase + st * B_STG;
        #pragma unroll
        for (int q = 0; q < 4; q++) {
            int c  = q * 256 + tid;
            int m  = c >> 3;
            int k4 = (c & 7) << 2;
            int kg = kbase + k4;
            const float* src;
            if (CONCAT) {
                int r = rowbase + m;
                if (kg < PF)      src = A0 + (size_t)r * PF + kg;
                else if (kg < K0) src = A1 + (size_t)r * NN + (kg - PF);
                else              src = g_zero4;
            } else {
                src = g_x + (((size_t)(rowbase + m)) << 7) + kg;
            }
            cp16(&As[m * A_LD + k4], src);
        }
        #pragma unroll
        for (int q = 0; q < 4; q++) {
            int c  = q * 256 + tid;
            int k  = c >> 5;
            int n4 = (c & 31) << 2;
            int kg = kbase + k;
            const float* src = (kg < KDIM) ? (W + (size_t)kg * DD + n4)
                                           : (const float*)g_zero4;
            cp16(&Bs[k * B_LD + n4], src);
        }
    };

    stage_load(0, 0); cp_commit();
    stage_load(1, 1); cp_commit();

    for (int kt = 0; kt < NT; kt++) {
        int buf = kt % 3;
        cp_wait1();
        __syncthreads();
        if (kt + 2 < NT) stage_load(kt + 2, (kt + 2) % 3);
        cp_commit();
        const float* As = Abase + buf * A_STG;
        const float* Bs = Bbase + buf * B_STG;
        #pragma unroll
        for (int kf = 0; kf < 4; kf++) {
            wmma::fragment<wmma::matrix_a, 16, 16, 8, wmma::precision::tf32, wmma::row_major> af[4];
            wmma::fragment<wmma::matrix_b, 16, 16, 8, wmma::precision::tf32, wmma::row_major> bf[2];
            #pragma unroll
            for (int a = 0; a < 4; a++) {
                wmma::load_matrix_sync(af[a], As + (wm * 64 + a * 16) * A_LD + kf * 8, A_LD);
                if (CONCAT) round_tf32(af[a]);   // raw inputs need RN; g_x pre-rounded
            }
            #pragma unroll
            for (int b = 0; b < 2; b++)
                wmma::load_matrix_sync(bf[b], Bs + (kf * 8) * B_LD + wn * 32 + b * 16, B_LD);
            #pragma unroll
            for (int a = 0; a < 4; a++)
                #pragma unroll
                for (int b = 0; b < 2; b++)
                    wmma::mma_sync(acc[a][b], af[a], bf[b], acc[a][b]);
        }
    }

    #pragma unroll
    for (int a = 0; a < 4; a++)
        #pragma unroll
        for (int b = 0; b < 2; b++) {
            float* p = g_y + (size_t)(rowbase + wm * 64 + a * 16) * DD + wn * 32 + b * 16;
            wmma::store_matrix_sync(p, acc[a][b], DD, wmma::mem_row_major);
        }
}

// ---------------- 3) sparse normalized aggregation + bias -------------------
// 1024 threads (32 warps -> 50% occ; latency hiding was the r15 binder).
// Block = (graph, 64-feature half). ysh = 513 rows (row 512 = sentinel zeros).
// Padded lists -> branch-free unroll-8 inner loop, packed add.rn.f32x2,
// 2 accumulators. Warp = row, stride 32.
#define AGG_THREADS 1024
#define AGG_SMEM_BYTES ((NN + 1) * 64 * 4)   // 131328
__global__ void __launch_bounds__(AGG_THREADS, 1)
aggregate(const float* __restrict__ bias, int do_round) {
    extern __shared__ float ysh[];   // (NN+1) x 64
    int s   = blockIdx.x;
    int f0  = blockIdx.y * 64;
    int tid = threadIdx.x;
    int lane = tid & 31, warp = tid >> 5;
    size_t sbase = (size_t)s * NN;

    #pragma unroll
    for (int q = 0; q < 8; q++) {
        int e = q * AGG_THREADS + tid;
        int r = e >> 4, c = e & 15;
        float4 v = *(const float4*)&g_y[((sbase + r) << 7) + f0 + (c << 2)];
        float d = g_dinv[sbase + r];
        v.x *= d; v.y *= d; v.z *= d; v.w *= d;
        *(float4*)&ysh[(r << 6) + (c << 2)] = v;
    }
    if (tid < 64) ysh[(NN << 6) + tid] = 0.0f;   // sentinel zero row
    __syncthreads();

    const unsigned long long* ysh64 = (const unsigned long long*)ysh;
    float2 bl = *(const float2*)&bias[f0 + lane * 2];

    for (int r = warp; r < NN; r += 32) {
        int cnt = g_cnt[sbase + r];          // padded, multiple of 8
        const int* nb = g_nbr + (size_t)(sbase + r) * MAXD;
        unsigned long long a0 = 0ull, a1 = 0ull;
        for (int base = 0; base < cnt; base += 32) {
            int idx = nb[base + lane];       // list region always readable
            int n8 = min(32, cnt - base) >> 3;
            for (int c8 = 0; c8 < n8; c8++) {
                #pragma unroll
                for (int k = 0; k < 8; k++) {
                    int j = __shfl_sync(0xffffffffu, idx, c8 * 8 + k);
                    unsigned long long v = ysh64[((unsigned)j << 5) + lane];
                    if (k & 1) addf32x2(a1, v); else addf32x2(a0, v);
                }
            }
        }
        float2 f0v = *(float2*)&a0;
        float2 f1v = *(float2*)&a1;
        float di = g_dinv[sbase + r];
        float2 o;
        o.x = di * (f0v.x + f1v.x) + bl.x;
        o.y = di * (f0v.y + f1v.y) + bl.y;
        if (do_round) {
            o.x = wmma::__float_to_tf32(o.x);
            o.y = wmma::__float_to_tf32(o.y);
        }
        *(float2*)&g_x[((sbase + r) << 7) + f0 + lane * 2] = o;
    }
}

// ---------------- 4) pool + softplus + MLP head ------------------------------
__global__ void head_kernel(const float* __restrict__ Wh, const float* __restrict__ bh,
                            const float* __restrict__ Wi, const float* __restrict__ bi,
                            const float* __restrict__ We, const float* __restrict__ be,
                            const float* __restrict__ Wlb, const float* __restrict__ blb,
                            const float* __restrict__ Wub, const float* __restrict__ bub,
                            float* __restrict__ out) {
    __shared__ float part[256];
    __shared__ float sp[DD];
    __shared__ float hsh[HID];
    int s = blockIdx.x, tid = threadIdx.x;
    int f = tid & (DD - 1);
    int half = tid >> 7;
    size_t base = (size_t)s * NN * DD;
    float acc = 0.0f;
    for (int i = half * 256; i < half * 256 + 256; i++)
        acc += g_x[base + (size_t)i * DD + f];
    part[tid] = acc;
    __syncthreads();
    if (tid < DD) {
        float v = part[tid] + part[tid + 128];
        sp[tid] = (v > 20.0f) ? v : log1pf(expf(v));
    }
    __syncthreads();
    {
        float a = bh[tid];
        #pragma unroll 4
        for (int k = 0; k < DD; k++) a += sp[k] * Wh[k * HID + tid];
        hsh[tid] = a;
    }
    __syncthreads();
    if (tid < 100) {
        float a = bi[tid];
        #pragma unroll 4
        for (int k = 0; k < HID; k++) a += hsh[k] * Wi[k * 100 + tid];
        out[s * 100 + tid] = a;
    } else if (tid < 103) {
        const float* Wv = (tid == 100) ? We : (tid == 101) ? Wlb : Wub;
        float bv = (tid == 100) ? be[0] : (tid == 101) ? blb[0] : bub[0];
        float a = bv;
        for (int k = 0; k < HID; k++) a += hsh[k] * Wv[k];
        out[SB * 100 + (tid - 100) * SB + s] = a;
    }
}

// ---------------- launch -----------------------------------------------------
extern "C" void kernel_launch(void* const* d_in, const int* in_sizes, int n_in,
                              void* d_out, int out_size) {
    const float* node = (const float*)d_in[0];
    const float* bond = (const float*)d_in[1];
    const int*   conn = (const int*)d_in[2];
    const float* W0 = (const float*)d_in[4];
    const float* b0 = (const float*)d_in[5];
    const float* W1 = (const float*)d_in[6];
    const float* b1 = (const float*)d_in[7];
    const float* W2 = (const float*)d_in[8];
    const float* b2 = (const float*)d_in[9];
    const float* Wh = (const float*)d_in[10];
    const float* bh = (const float*)d_in[11];
    const float* Wi = (const float*)d_in[12];
    const float* bi = (const float*)d_in[13];
    const float* We = (const float*)d_in[14];
    const float* be = (const float*)d_in[15];
    const float* Wlb = (const float*)d_in[16];
    const float* blb = (const float*)d_in[17];
    const float* Wub = (const float*)d_in[18];
    const float* bub = (const float*)d_in[19];
    float* out = (float*)d_out;

    static bool configured = false;
    static float *w0r, *w1r, *w2r;
    if (!configured) {
        cudaFuncSetAttribute(aggregate, cudaFuncAttributeMaxDynamicSharedMemorySize, AGG_SMEM_BYTES);
        cudaFuncSetAttribute(gemm_wmma<K0, true>,
                             cudaFuncAttributeMaxDynamicSharedMemorySize, GEMM_SMEM_BYTES);
        cudaFuncSetAttribute(gemm_wmma<DD, false>,
                             cudaFuncAttributeMaxDynamicSharedMemorySize, GEMM_SMEM_BYTES);
        cudaGetSymbolAddress((void**)&w0r, g_w0r);
        cudaGetSymbolAddress((void**)&w1r, g_w1r);
        cudaGetSymbolAddress((void**)&w2r, g_w2r);
        configured = true;
    }

    dim3 aggGrid(SB, 2);

    round_weights<<<(K0 * DD + 255) / 256, 256>>>(W0, W1, W2);
    build_adj<<<ROWS / 8, 256>>>(conn);

    gemm_wmma<K0, true><<<ROWS / 128, 256, GEMM_SMEM_BYTES>>>(node, bond, w0r);
    aggregate<<<aggGrid, AGG_THREADS, AGG_SMEM_BYTES>>>(b0, 1);

    gemm_wmma<DD, false><<<ROWS / 128, 256, GEMM_SMEM_BYTES>>>(nullptr, nullptr, w1r);
    aggregate<<<aggGrid, AGG_THREADS, AGG_SMEM_BYTES>>>(b1, 1);

    gemm_wmma<DD, false><<<ROWS / 128, 256, GEMM_SMEM_BYTES>>>(nullptr, nullptr, w2r);
    aggregate<<<aggGrid, AGG_THREADS, AGG_SMEM_BYTES>>>(b2, 0);

    head_kernel<<<SB, 256>>>(Wh, bh, Wi, bi, We, be, Wlb, blb, Wub, bub, out);
}

// round 17
// speedup vs baseline: 1.1806x; 1.0073x over previous
#include <cuda_runtime.h>
#include <cstdint>
#include <mma.h>
#include <math.h>

using namespace nvcuda;

#define SB   128      // batch (graphs)
#define NN   512      // nodes per graph
#define PF   92       // node feature dim
#define K0   604      // PF + NN
#define DD   128      // hidden dim of GCN layers
#define HID  256
#define MAXD 96
#define ROWS (SB*NN)  // 65536

// ---------------- scratch (static device globals; no allocations) -----------
__device__ float g_dinv[ROWS];
__device__ int   g_cnt[ROWS];            // PADDED count (multiple of 4)
__device__ int   g_nbr[(size_t)ROWS*MAXD];
__device__ float g_x[(size_t)ROWS*DD];   // post-aggregation activations
__device__ float g_y[(size_t)ROWS*DD];   // pre-aggregation (XW) results
__device__ float g_w0r[K0*DD];           // tf32-pre-rounded weights
__device__ float g_w1r[DD*DD];
__device__ float g_w2r[DD*DD];
__device__ __align__(16) float g_zero4[4];   // zero-filled quad for OOB cp.async

// ---------------- helpers ----------------------------------------------------
__device__ __forceinline__ void cp16(void* smem_dst, const void* gmem_src) {
    unsigned int s = (unsigned int)__cvta_generic_to_shared(smem_dst);
    asm volatile("cp.async.cg.shared.global [%0], [%1], 16;\n" :: "r"(s), "l"(gmem_src));
}
__device__ __forceinline__ void cp_commit() {
    asm volatile("cp.async.commit_group;\n" ::: "memory");
}
__device__ __forceinline__ void cp_wait1() {
    asm volatile("cp.async.wait_group 1;\n" ::: "memory");
}
__device__ __forceinline__ void addf32x2(unsigned long long& acc, unsigned long long v) {
    asm("add.rn.f32x2 %0, %1, %2;" : "=l"(acc) : "l"(acc), "l"(v));
}

// ---------------- 0) pre-round weights to tf32 (RN) -------------------------
__global__ void round_weights(const float* __restrict__ W0,
                              const float* __restrict__ W1,
                              const float* __restrict__ W2) {
    int i = blockIdx.x * 256 + threadIdx.x;
    if (i < K0 * DD) g_w0r[i] = wmma::__float_to_tf32(W0[i]);
    if (i < DD * DD) {
        g_w1r[i] = wmma::__float_to_tf32(W1[i]);
        g_w2r[i] = wmma::__float_to_tf32(W2[i]);
    }
}

// ---------------- 1) adjacency lists + deg^{-1/2} ---------------------------
// Ahat = (conn!=0) + I (diag may be 2 -> self appears twice).
// List = real neighbors (capped 87) + self + sentinel NN pads to multiple of 4.
__global__ void build_adj(const int* __restrict__ conn) {
    int warp = (blockIdx.x * blockDim.x + threadIdx.x) >> 5;
    int lane = threadIdx.x & 31;
    if (warp >= ROWS) return;
    int i = warp & (NN - 1);
    const int4* row4 = (const int4*)(conn + (size_t)warp * NN);
    int cnt = 0;
    #pragma unroll
    for (int t = 0; t < 4; t++) {
        int4 v4 = row4[lane + t * 32];
        int vv[4] = {v4.x, v4.y, v4.z, v4.w};
        #pragma unroll
        for (int w = 0; w < 4; w++) {
            int v = (vv[w] != 0);
            unsigned m = __ballot_sync(0xffffffffu, v);
            if (v) {
                int pos = cnt + __popc(m & ((1u << lane) - 1u));
                if (pos < MAXD - 9)
                    g_nbr[(size_t)warp * MAXD + pos] = (lane + t * 32) * 4 + w;
            }
            cnt += __popc(m);
        }
    }
    if (lane == 0) {
        int c = cnt < (MAXD - 9) ? cnt : (MAXD - 9);   // cap 87
        size_t b = (size_t)warp * MAXD;
        g_nbr[b + c] = i;   // self loop (the +I)
        c++;
        while (c & 3) g_nbr[b + c++] = NN;   // sentinel -> zero row, pad %4
        g_cnt[warp] = c;
        g_dinv[warp] = rsqrtf((float)(cnt + 1));
    }
}

// ---------------- 2) tf32 WMMA GEMM, cp.async 3-stage pipeline --------------
#define KT      32
#define A_LD    36
#define B_LD    132
#define A_STG   (128 * A_LD)
#define B_STG   (KT * B_LD)
#define GEMM_SMEM_BYTES ((3 * (A_STG + B_STG)) * 4)   // 105984

template<class Frag>
__device__ __forceinline__ void round_tf32(Frag& f) {
    #pragma unroll
    for (int i = 0; i < f.num_elements; i++)
        f.x[i] = wmma::__float_to_tf32(f.x[i]);
}

template<int KDIM, bool CONCAT>
__global__ void __launch_bounds__(256, 2)
gemm_wmma(const float* __restrict__ A0,
          const float* __restrict__ A1,
          const float* __restrict__ W) {
    constexpr int NT = (KDIM + KT - 1) / KT;
    extern __shared__ float smem[];
    float* Abase = smem;
    float* Bbase = smem + 3 * A_STG;

    int tid  = threadIdx.x;
    int warp = tid >> 5;
    int wm   = warp & 1;
    int wn   = warp >> 1;
    int rowbase = blockIdx.x * 128;

    wmma::fragment<wmma::accumulator, 16, 16, 8, float> acc[4][2];
    #pragma unroll
    for (int a = 0; a < 4; a++)
        #pragma unroll
        for (int b = 0; b < 2; b++)
            wmma::fill_fragment(acc[a][b], 0.0f);

    auto stage_load = [&](int kt, int st) {
        int kbase = kt * KT;
        float* As = Abase + st * A_STG;
        float* Bs = Bbase + st * B_STG;
        #pragma unroll
        for (int q = 0; q < 4; q++) {
            int c  = q * 256 + tid;
            int m  = c >> 3;
            int k4 = (c & 7) << 2;
            int kg = kbase + k4;
            const float* src;
            if (CONCAT) {
                int r = rowbase + m;
                if (kg < PF)      src = A0 + (size_t)r * PF + kg;
                else if (kg < K0) src = A1 + (size_t)r * NN + (kg - PF);
                else              src = g_zero4;
            } else {
                src = g_x + (((size_t)(rowbase + m)) << 7) + kg;
            }
            cp16(&As[m * A_LD + k4], src);
        }
        #pragma unroll
        for (int q = 0; q < 4; q++) {
            int c  = q * 256 + tid;
            int k  = c >> 5;
            int n4 = (c & 31) << 2;
            int kg = kbase + k;
            const float* src = (kg < KDIM) ? (W + (size_t)kg * DD + n4)
                                           : (const float*)g_zero4;
            cp16(&Bs[k * B_LD + n4], src);
        }
    };

    stage_load(0, 0); cp_commit();
    stage_load(1, 1); cp_commit();

    for (int kt = 0; kt < NT; kt++) {
        int buf = kt % 3;
        cp_wait1();
        __syncthreads();
        if (kt + 2 < NT) stage_load(kt + 2, (kt + 2) % 3);
        cp_commit();
        const float* As = Abase + buf * A_STG;
        const float* Bs = Bbase + buf * B_STG;
        #pragma unroll
        for (int kf = 0; kf < 4; kf++) {
            wmma::fragment<wmma::matrix_a, 16, 16, 8, wmma::precision::tf32, wmma::row_major> af[4];
            wmma::fragment<wmma::matrix_b, 16, 16, 8, wmma::precision::tf32, wmma::row_major> bf[2];
            #pragma unroll
            for (int a = 0; a < 4; a++) {
                wmma::load_matrix_sync(af[a], As + (wm * 64 + a * 16) * A_LD + kf * 8, A_LD);
                if (CONCAT) round_tf32(af[a]);   // raw inputs need RN; g_x pre-rounded
            }
            #pragma unroll
            for (int b = 0; b < 2; b++)
                wmma::load_matrix_sync(bf[b], Bs + (kf * 8) * B_LD + wn * 32 + b * 16, B_LD);
            #pragma unroll
            for (int a = 0; a < 4; a++)
                #pragma unroll
                for (int b = 0; b < 2; b++)
                    wmma::mma_sync(acc[a][b], af[a], bf[b], acc[a][b]);
        }
    }

    #pragma unroll
    for (int a = 0; a < 4; a++)
        #pragma unroll
        for (int b = 0; b < 2; b++) {
            float* p = g_y + (size_t)(rowbase + wm * 64 + a * 16) * DD + wn * 32 + b * 16;
            wmma::store_matrix_sync(p, acc[a][b], DD, wmma::mem_row_major);
        }
}

// ---------------- 3) sparse normalized aggregation + bias -------------------
// 1024 threads (32 warps, smem-capped occupancy). Block = (graph, 64-feat
// half). ysh = 513 rows (row 512 = sentinel zeros). %4-padded lists ->
// branch-free unroll-4 inner loop, packed add.rn.f32x2, 2 accumulators.
#define AGG_THREADS 1024
#define AGG_SMEM_BYTES ((NN + 1) * 64 * 4)   // 131328
__global__ void __launch_bounds__(AGG_THREADS, 1)
aggregate(const float* __restrict__ bias, int do_round) {
    extern __shared__ float ysh[];   // (NN+1) x 64
    int s   = blockIdx.x;
    int f0  = blockIdx.y * 64;
    int tid = threadIdx.x;
    int lane = tid & 31, warp = tid >> 5;
    size_t sbase = (size_t)s * NN;

    #pragma unroll
    for (int q = 0; q < 8; q++) {
        int e = q * AGG_THREADS + tid;
        int r = e >> 4, c = e & 15;
        float4 v = *(const float4*)&g_y[((sbase + r) << 7) + f0 + (c << 2)];
        float d = g_dinv[sbase + r];
        v.x *= d; v.y *= d; v.z *= d; v.w *= d;
        *(float4*)&ysh[(r << 6) + (c << 2)] = v;
    }
    if (tid < 64) ysh[(NN << 6) + tid] = 0.0f;   // sentinel zero row
    __syncthreads();

    const unsigned long long* ysh64 = (const unsigned long long*)ysh;
    float2 bl = *(const float2*)&bias[f0 + lane * 2];

    for (int r = warp; r < NN; r += 32) {
        int cnt = g_cnt[sbase + r];          // padded, multiple of 4
        const int* nb = g_nbr + (size_t)(sbase + r) * MAXD;
        unsigned long long a0 = 0ull, a1 = 0ull;
        for (int base = 0; base < cnt; base += 32) {
            int idx = nb[base + lane];       // list region always readable
            int n4 = min(32, cnt - base) >> 2;
            for (int c4 = 0; c4 < n4; c4++) {
                #pragma unroll
                for (int k = 0; k < 4; k++) {
                    int j = __shfl_sync(0xffffffffu, idx, c4 * 4 + k);
                    unsigned long long v = ysh64[((unsigned)j << 5) + lane];
                    if (k & 1) addf32x2(a1, v); else addf32x2(a0, v);
                }
            }
        }
        float2 f0v = *(float2*)&a0;
        float2 f1v = *(float2*)&a1;
        float di = g_dinv[sbase + r];
        float2 o;
        o.x = di * (f0v.x + f1v.x) + bl.x;
        o.y = di * (f0v.y + f1v.y) + bl.y;
        if (do_round) {
            o.x = wmma::__float_to_tf32(o.x);
            o.y = wmma::__float_to_tf32(o.y);
        }
        *(float2*)&g_x[((sbase + r) << 7) + f0 + lane * 2] = o;
    }
}

// ---------------- 4) pool + softplus + MLP head ------------------------------
__global__ void head_kernel(const float* __restrict__ Wh, const float* __restrict__ bh,
                            const float* __restrict__ Wi, const float* __restrict__ bi,
                            const float* __restrict__ We, const float* __restrict__ be,
                            const float* __restrict__ Wlb, const float* __restrict__ blb,
                            const float* __restrict__ Wub, const float* __restrict__ bub,
                            float* __restrict__ out) {
    __shared__ float part[256];
    __shared__ float sp[DD];
    __shared__ float hsh[HID];
    int s = blockIdx.x, tid = threadIdx.x;
    int f = tid & (DD - 1);
    int half = tid >> 7;
    size_t base = (size_t)s * NN * DD;
    float acc = 0.0f;
    for (int i = half * 256; i < half * 256 + 256; i++)
        acc += g_x[base + (size_t)i * DD + f];
    part[tid] = acc;
    __syncthreads();
    if (tid < DD) {
        float v = part[tid] + part[tid + 128];
        sp[tid] = (v > 20.0f) ? v : log1pf(expf(v));
    }
    __syncthreads();
    {
        float a = bh[tid];
        #pragma unroll 4
        for (int k = 0; k < DD; k++) a += sp[k] * Wh[k * HID + tid];
        hsh[tid] = a;
    }
    __syncthreads();
    if (tid < 100) {
        float a = bi[tid];
        #pragma unroll 4
        for (int k = 0; k < HID; k++) a += hsh[k] * Wi[k * 100 + tid];
        out[s * 100 + tid] = a;
    } else if (tid < 103) {
        const float* Wv = (tid == 100) ? We : (tid == 101) ? Wlb : Wub;
        float bv = (tid == 100) ? be[0] : (tid == 101) ? blb[0] : bub[0];
        float a = bv;
        for (int k = 0; k < HID; k++) a += hsh[k] * Wv[k];
        out[SB * 100 + (tid - 100) * SB + s] = a;
    }
}

// ---------------- launch -----------------------------------------------------
extern "C" void kernel_launch(void* const* d_in, const int* in_sizes, int n_in,
                              void* d_out, int out_size) {
    const float* node = (const float*)d_in[0];
    const float* bond = (const float*)d_in[1];
    const int*   conn = (const int*)d_in[2];
    const float* W0 = (const float*)d_in[4];
    const float* b0 = (const float*)d_in[5];
    const float* W1 = (const float*)d_in[6];
    const float* b1 = (const float*)d_in[7];
    const float* W2 = (const float*)d_in[8];
    const float* b2 = (const float*)d_in[9];
    const float* Wh = (const float*)d_in[10];
    const float* bh = (const float*)d_in[11];
    const float* Wi = (const float*)d_in[12];
    const float* bi = (const float*)d_in[13];
    const float* We = (const float*)d_in[14];
    const float* be = (const float*)d_in[15];
    const float* Wlb = (const float*)d_in[16];
    const float* blb = (const float*)d_in[17];
    const float* Wub = (const float*)d_in[18];
    const float* bub = (const float*)d_in[19];
    float* out = (float*)d_out;

    static bool configured = false;
    static float *w0r, *w1r, *w2r;
    static cudaStream_t s_side;
    static cudaEvent_t evFork, evJoin;
    if (!configured) {
        cudaFuncSetAttribute(aggregate, cudaFuncAttributeMaxDynamicSharedMemorySize, AGG_SMEM_BYTES);
        cudaFuncSetAttribute(gemm_wmma<K0, true>,
                             cudaFuncAttributeMaxDynamicSharedMemorySize, GEMM_SMEM_BYTES);
        cudaFuncSetAttribute(gemm_wmma<DD, false>,
                             cudaFuncAttributeMaxDynamicSharedMemorySize, GEMM_SMEM_BYTES);
        cudaGetSymbolAddress((void**)&w0r, g_w0r);
        cudaGetSymbolAddress((void**)&w1r, g_w1r);
        cudaGetSymbolAddress((void**)&w2r, g_w2r);
        cudaStreamCreateWithFlags(&s_side, cudaStreamNonBlocking);
        cudaEventCreateWithFlags(&evFork, cudaEventDisableTiming);
        cudaEventCreateWithFlags(&evJoin, cudaEventDisableTiming);
        configured = true;
    }

    dim3 aggGrid(SB, 2);

    // Fork: build_adj (DRAM stream) runs on the side stream, concurrent with
    // round_weights + gemm604 (compute-bound) on the main stream.
    cudaEventRecord(evFork, 0);
    cudaStreamWaitEvent(s_side, evFork, 0);
    build_adj<<<ROWS / 8, 256, 0, s_side>>>(conn);
    cudaEventRecord(evJoin, s_side);

    round_weights<<<(K0 * DD + 255) / 256, 256>>>(W0, W1, W2);
    gemm_wmma<K0, true><<<ROWS / 128, 256, GEMM_SMEM_BYTES>>>(node, bond, w0r);

    // Join: aggregate needs build_adj's lists/dinv.
    cudaStreamWaitEvent(0, evJoin, 0);
    aggregate<<<aggGrid, AGG_THREADS, AGG_SMEM_BYTES>>>(b0, 1);

    gemm_wmma<DD, false><<<ROWS / 128, 256, GEMM_SMEM_BYTES>>>(nullptr, nullptr, w1r);
    aggregate<<<aggGrid, AGG_THREADS, AGG_SMEM_BYTES>>>(b1, 1);

    gemm_wmma<DD, false><<<ROWS / 128, 256, GEMM_SMEM_BYTES>>>(nullptr, nullptr, w2r);
    aggregate<<<aggGrid, AGG_THREADS, AGG_SMEM_BYTES>>>(b2, 0);

    head_kernel<<<SB, 256>>>(Wh, bh, Wi, bi, We, be, Wlb, blb, Wub, bub, out);
}